// round 3
// baseline (speedup 1.0000x reference)
#include <cuda_runtime.h>

// Problem geometry
#define T_  20
#define B_  8
#define C_  3
#define H_  256
#define W_  256
#define OH  252
#define OW  252

// Physics constants (float32, matching reference)
#define DT_      0.05f          // 10/200
#define INV_DT   20.0f          // 1/DT
#define INV_2DT  10.0f          // 1/(2*DT)
#define INV_DX2  40.96f         // 1/( (20/128)^2 ) = 1/0.0244140625
#define DU_      0.16f
#define DV_      0.08f
#define FF_      0.06f
#define FK_      0.122f         // f + k

__global__ __launch_bounds__(256) void gray_scott_residual_kernel(
    const float* __restrict__ in,   // (T,B,3,H,W)
    float* __restrict__ out)        // f_u (T,B,1,OH,OW) then f_v
{
    const int j  = blockIdx.x * blockDim.x + threadIdx.x;   // 0..OW-1
    const int i  = blockIdx.y * blockDim.y + threadIdx.y;   // 0..OH-1
    const int tb = blockIdx.z;                               // 0..T*B-1
    if (i >= OH || j >= OW) return;

    const int t = tb / B_;

    const long planeHW = (long)H_ * W_;
    const long tstride = (long)B_ * C_ * planeHW;           // elements between time steps

    const float* __restrict__ up = in + ((long)tb * C_ + 1) * planeHW;  // u plane (t,b)
    const float* __restrict__ vp = up + planeHW;                         // v plane (t,b)

    // center of the 5x5 window for output (i,j) is input (i+2, j+2)
    const int ci = (i + 2) * W_ + (j + 2);

    // ---- Laplacian taps (4th-order cross stencil) ----
    // coefficients: center -5, +/-1: 4/3, +/-2: -1/12 (per axis), all / DX^2
    const float c1 = 4.0f / 3.0f;
    const float c2 = -1.0f / 12.0f;

    const float u_c  = __ldg(up + ci);
    const float u_w1 = __ldg(up + ci - 1);
    const float u_e1 = __ldg(up + ci + 1);
    const float u_w2 = __ldg(up + ci - 2);
    const float u_e2 = __ldg(up + ci + 2);
    const float u_n1 = __ldg(up + ci - W_);
    const float u_s1 = __ldg(up + ci + W_);
    const float u_n2 = __ldg(up + ci - 2 * W_);
    const float u_s2 = __ldg(up + ci + 2 * W_);

    const float v_c  = __ldg(vp + ci);
    const float v_w1 = __ldg(vp + ci - 1);
    const float v_e1 = __ldg(vp + ci + 1);
    const float v_w2 = __ldg(vp + ci - 2);
    const float v_e2 = __ldg(vp + ci + 2);
    const float v_n1 = __ldg(vp + ci - W_);
    const float v_s1 = __ldg(vp + ci + W_);
    const float v_n2 = __ldg(vp + ci - 2 * W_);
    const float v_s2 = __ldg(vp + ci + 2 * W_);

    float lap_u = (c2 * (u_w2 + u_e2 + u_n2 + u_s2)
                 + c1 * (u_w1 + u_e1 + u_n1 + u_s1)
                 - 5.0f * u_c) * INV_DX2;
    float lap_v = (c2 * (v_w2 + v_e2 + v_n2 + v_s2)
                 + c1 * (v_w1 + v_e1 + v_n1 + v_s1)
                 - 5.0f * v_c) * INV_DX2;

    // ---- Time derivatives at the center point ----
    float u_t, v_t;
    if (t == 0) {
        const float u1 = __ldg(up + ci + tstride);
        const float u2 = __ldg(up + ci + 2 * tstride);
        const float v1 = __ldg(vp + ci + tstride);
        const float v2 = __ldg(vp + ci + 2 * tstride);
        u_t = (-1.5f * u_c + 2.0f * u1 - 0.5f * u2) * INV_DT;
        v_t = (-1.5f * v_c + 2.0f * v1 - 0.5f * v2) * INV_DT;
    } else if (t == T_ - 1) {
        const float um1 = __ldg(up + ci - tstride);
        const float um2 = __ldg(up + ci - 2 * tstride);
        const float vm1 = __ldg(vp + ci - tstride);
        const float vm2 = __ldg(vp + ci - 2 * tstride);
        u_t = (0.5f * um2 - 2.0f * um1 + 1.5f * u_c) * INV_DT;
        v_t = (0.5f * vm2 - 2.0f * vm1 + 1.5f * v_c) * INV_DT;
    } else {
        const float up1 = __ldg(up + ci + tstride);
        const float um1 = __ldg(up + ci - tstride);
        const float vp1 = __ldg(vp + ci + tstride);
        const float vm1 = __ldg(vp + ci - tstride);
        u_t = (up1 - um1) * INV_2DT;
        v_t = (vp1 - vm1) * INV_2DT;
    }

    // ---- Residuals ----
    const float uvv = u_c * v_c * v_c;
    const float f_u = DU_ * lap_u - uvv + FF_ * (1.0f - u_c) - u_t;
    const float f_v = DV_ * lap_v + uvv - FK_ * v_c - v_t;

    const long oplane = (long)OH * OW;
    const long oidx   = (long)tb * oplane + (long)i * OW + j;
    out[oidx]                         = f_u;   // f_u block
    out[oidx + (long)T_ * B_ * oplane] = f_v;  // f_v block
}

extern "C" void kernel_launch(void* const* d_in, const int* in_sizes, int n_in,
                              void* d_out, int out_size)
{
    const float* in = (const float*)d_in[0];
    float* out = (float*)d_out;

    dim3 block(64, 4, 1);
    dim3 grid((OW + 63) / 64, (OH + 3) / 4, T_ * B_);
    gray_scott_residual_kernel<<<grid, block>>>(in, out);
}

// round 4
// speedup vs baseline: 1.7018x; 1.7018x over previous
#include <cuda_runtime.h>

// Problem geometry
#define T_   20
#define B_   8
#define H_   256
#define W_   256
#define OH   252
#define OW   252
#define PLANE    65536L                 // H_*W_
#define TSTRIDE  (3L * B_ * PLANE)      // elements between time steps
#define OPLANE   ((long)OH * OW)        // 63504

// Physics constants (float32, matching reference)
#define INV_DT   20.0f
#define INV_2DT  10.0f
#define INV_DX2  40.96f
#define DU_      0.16f
#define DV_      0.08f
#define FF_      0.06f
#define FK_      0.122f                 // f + k
#define C1v      1.3333333333333333f    // 4/3
#define C2v      (-0.08333333333333333f)// -1/12

// Load 4 center-column floats (cols +2..+5 relative to p) via two 8B loads.
__device__ __forceinline__ void ld_c4(const float* __restrict__ p, float c[4]) {
    float2 a = __ldg((const float2*)(p + 2));
    float2 b = __ldg((const float2*)(p + 4));
    c[0] = a.x; c[1] = a.y; c[2] = b.x; c[3] = b.y;
}

// Load 8 contiguous floats (cols +0..+7) via two 16B loads.
__device__ __forceinline__ void ld_f8(const float* __restrict__ p, float f[8]) {
    float4 a = __ldg((const float4*)(p));
    float4 b = __ldg((const float4*)(p + 4));
    f[0] = a.x; f[1] = a.y; f[2] = a.z; f[3] = a.w;
    f[4] = b.x; f[5] = b.y; f[6] = b.z; f[7] = b.w;
}

// Process one variable (u or v) over a 4x2 output tile.
// plane: pointer to this (t,b) plane; rb: element offset of stencil-top-left row/col.
// Outputs: lap[r][k] (scaled Laplacian), cc[r][k] (center value), td[r][k] (time deriv).
__device__ __forceinline__ void proc_var(const float* __restrict__ plane, int t, int rb,
                                         float lap[2][4], float cc[2][4], float td[2][4]) {
    float r0[4], r1[4], r4[4], r5[4], f2[8], f3[8];
    ld_c4(plane + rb,          r0);   // row i   (n2 for out-row 0)
    ld_c4(plane + rb + W_,     r1);   // row i+1
    ld_f8(plane + rb + 2*W_,   f2);   // row i+2 (center of out-row 0), full 8 cols
    ld_f8(plane + rb + 3*W_,   f3);   // row i+3 (center of out-row 1), full 8 cols
    ld_c4(plane + rb + 4*W_,   r4);   // row i+4
    ld_c4(plane + rb + 5*W_,   r5);   // row i+5

    #pragma unroll
    for (int k = 0; k < 4; k++) {
        lap[0][k] = (C2v * (r0[k] + r4[k]   + f2[k]   + f2[k+4])
                   + C1v * (r1[k] + f3[k+2] + f2[k+1] + f2[k+3])
                   - 5.0f * f2[k+2]) * INV_DX2;
        lap[1][k] = (C2v * (r1[k]   + r5[k] + f3[k]   + f3[k+4])
                   + C1v * (f2[k+2] + r4[k] + f3[k+1] + f3[k+3])
                   - 5.0f * f3[k+2]) * INV_DX2;
        cc[0][k] = f2[k+2];
        cc[1][k] = f3[k+2];
    }

    // Time derivative at center rows (i+2, i+3), cols +2..+5.
    float a0[4], a1[4], b0[4], b1[4];
    if (t == 0) {
        ld_c4(plane + rb + 2*W_ +     TSTRIDE, a0);
        ld_c4(plane + rb + 3*W_ +     TSTRIDE, a1);
        ld_c4(plane + rb + 2*W_ + 2 * TSTRIDE, b0);
        ld_c4(plane + rb + 3*W_ + 2 * TSTRIDE, b1);
        #pragma unroll
        for (int k = 0; k < 4; k++) {
            td[0][k] = (-1.5f * cc[0][k] + 2.0f * a0[k] - 0.5f * b0[k]) * INV_DT;
            td[1][k] = (-1.5f * cc[1][k] + 2.0f * a1[k] - 0.5f * b1[k]) * INV_DT;
        }
    } else if (t == T_ - 1) {
        ld_c4(plane + rb + 2*W_ -     TSTRIDE, a0);
        ld_c4(plane + rb + 3*W_ -     TSTRIDE, a1);
        ld_c4(plane + rb + 2*W_ - 2 * TSTRIDE, b0);
        ld_c4(plane + rb + 3*W_ - 2 * TSTRIDE, b1);
        #pragma unroll
        for (int k = 0; k < 4; k++) {
            td[0][k] = (0.5f * b0[k] - 2.0f * a0[k] + 1.5f * cc[0][k]) * INV_DT;
            td[1][k] = (0.5f * b1[k] - 2.0f * a1[k] + 1.5f * cc[1][k]) * INV_DT;
        }
    } else {
        ld_c4(plane + rb + 2*W_ + TSTRIDE, a0);
        ld_c4(plane + rb + 3*W_ + TSTRIDE, a1);
        ld_c4(plane + rb + 2*W_ - TSTRIDE, b0);
        ld_c4(plane + rb + 3*W_ - TSTRIDE, b1);
        #pragma unroll
        for (int k = 0; k < 4; k++) {
            td[0][k] = (a0[k] - b0[k]) * INV_2DT;
            td[1][k] = (a1[k] - b1[k]) * INV_2DT;
        }
    }
}

__global__ __launch_bounds__(256) void gray_scott_residual_v2(
    const float* __restrict__ in,   // (T,B,3,H,W)
    float* __restrict__ out)        // f_u (T,B,1,OH,OW) then f_v
{
    const int gx = blockIdx.x * 32 + threadIdx.x;   // float4-column index, 0..62
    const int gy = blockIdx.y * 8  + threadIdx.y;   // row-pair index,     0..125
    const int tb = blockIdx.z;
    if (gx >= OW / 4 || gy >= OH / 2) return;

    const int j = gx * 4;          // output col base
    const int i = gy * 2;          // output row base
    const int t = tb >> 3;         // tb / B_

    const float* __restrict__ up = in + ((long)tb * 3 + 1) * PLANE;
    const float* __restrict__ vp = up + PLANE;

    const int rb = i * W_ + j;     // stencil top-left (input row i, col j)

    // ---- u phase: fold into partial f_u immediately to free registers ----
    float lap[2][4], uc[2][4], td[2][4];
    proc_var(up, t, rb, lap, uc, td);

    float fupart[2][4];
    #pragma unroll
    for (int r = 0; r < 2; r++)
        #pragma unroll
        for (int k = 0; k < 4; k++)
            fupart[r][k] = DU_ * lap[r][k] + FF_ * (1.0f - uc[r][k]) - td[r][k];

    // ---- v phase ----
    float vc[2][4];
    proc_var(vp, t, rb, lap, vc, td);

    float fu[2][4], fv[2][4];
    #pragma unroll
    for (int r = 0; r < 2; r++)
        #pragma unroll
        for (int k = 0; k < 4; k++) {
            const float uvv = uc[r][k] * vc[r][k] * vc[r][k];
            fu[r][k] = fupart[r][k] - uvv;
            fv[r][k] = DV_ * lap[r][k] + uvv - FK_ * vc[r][k] - td[r][k];
        }

    // ---- vectorized stores ----
    const long ob = (long)tb * OPLANE + (long)i * OW + j;
    float* __restrict__ ou = out + ob;
    float* __restrict__ ov = out + ob + (long)T_ * B_ * OPLANE;

    *(float4*)(ou)      = make_float4(fu[0][0], fu[0][1], fu[0][2], fu[0][3]);
    *(float4*)(ou + OW) = make_float4(fu[1][0], fu[1][1], fu[1][2], fu[1][3]);
    *(float4*)(ov)      = make_float4(fv[0][0], fv[0][1], fv[0][2], fv[0][3]);
    *(float4*)(ov + OW) = make_float4(fv[1][0], fv[1][1], fv[1][2], fv[1][3]);
}

extern "C" void kernel_launch(void* const* d_in, const int* in_sizes, int n_in,
                              void* d_out, int out_size)
{
    const float* in = (const float*)d_in[0];
    float* out = (float*)d_out;

    dim3 block(32, 8, 1);
    // x: 63 float4-columns -> 2 blocks of 32; y: 126 row-pairs -> 16 blocks of 8
    dim3 grid(2, 16, T_ * B_);
    gray_scott_residual_v2<<<grid, block>>>(in, out);
}